// round 13
// baseline (speedup 1.0000x reference)
#include <cuda_runtime.h>
#include <cuda_fp16.h>
#include <math.h>
#include <stdint.h>

#define T_ 1024
#define H_ 1024
#define I_ 1024
#define E_ 8
#define NP (T_*2)
#define HP (H_/2)      // 512 packed k-pairs per row
#define IP (I_/2)

#define BM 128
#define BN 64
#define BKP 16         // k-pairs per chunk (32 floats)
#define RS 20          // A smem row stride (words) — conflict-free frags
#define BST 72         // B smem kp-row stride (words) — conflict-free frags
#define MAXMT 16
#define NCH 32         // 512 kp / 16
#define NITEMS (E_*MAXMT*16)   // per phase: (e,mt) x 16 n-slabs
#define NBLK 148

// combine constants: D = (1 - 1/s)*C_HH + s*C_MM, s = 32
#define SC_C 0.96875f
#define SC_S 32.0f
#define SC_INV 0.03125f

// stage word offsets (within one stage)
#define OFF_AH 0
#define OFF_AM 2560
#define OFF_B0 5120          // g1: gate-H ; g2: w2-H
#define OFF_B1 6400          // g1: gate-M ; g2: w2-M
#define OFF_B2 7680          // g1: up-H
#define OFF_B3 8960          // g1: up-M
#define STW 10240            // stage words (union layout)
#define SM_BYTES ((128 + 2*STW)*4)

// ---- routing / scheduling scratch ----
__device__ float g_pair_w[NP];
__device__ int   g_offsets[E_+1];
__device__ int   g_perm[NP];
__device__ int   g_work;
__device__ int   g_done1[E_*MAXMT];

// ---- packed fp16 hi / scaled-residual operands (uint32 = half2 k-pair) ----
__device__ __align__(16) unsigned g_hidH[T_*HP],        g_hidM[T_*HP];        // [t][hp]
__device__ __align__(16) unsigned g_w13H[E_*HP*2*I_],   g_w13M[E_*HP*2*I_];   // [e][hp][2I]
__device__ __align__(16) unsigned g_w2H [E_*IP*H_],     g_w2M [E_*IP*H_];     // [e][ip][H]
__device__ __align__(16) unsigned g_actH[NP*IP],        g_actM[NP*IP];        // [p][ip]

// ---------------------------------------------------------------------------
__device__ __forceinline__ void split_pack16(float x, float y, unsigned& h, unsigned& m) {
    __half2 hv = __floats2half2_rn(x, y);
    h = *(unsigned*)&hv;
    float hx = __low2float(hv), hy = __high2float(hv);
    __half2 mv = __floats2half2_rn(hx * SC_INV + (x - hx), hy * SC_INV + (y - hy));
    m = *(unsigned*)&mv;
}
__device__ __forceinline__ uint32_t smem_u32(const void* p) {
    uint32_t a;
    asm("{ .reg .u64 t; cvta.to.shared.u64 t, %1; cvt.u32.u64 %0, t; }" : "=r"(a) : "l"(p));
    return a;
}
#define CP16(dst, src, sz) \
    asm volatile("cp.async.cg.shared.global [%0], [%1], 16, %2;" :: "r"(dst), "l"(src), "r"(sz) : "memory")
#define CP_COMMIT() asm volatile("cp.async.commit_group;" ::: "memory")
#define CP_WAIT0()  asm volatile("cp.async.wait_group 0;" ::: "memory")

#define MMA(c, a, b0_, b1_)                                                   \
    asm volatile("mma.sync.aligned.m16n8k16.row.col.f32.f16.f16.f32 "         \
        "{%0,%1,%2,%3}, {%4,%5,%6,%7}, {%8,%9}, {%0,%1,%2,%3};"               \
        : "+f"((c)[0]), "+f"((c)[1]), "+f"((c)[2]), "+f"((c)[3])              \
        : "r"((a)[0]), "r"((a)[1]), "r"((a)[2]), "r"((a)[3]),                 \
          "r"(b0_), "r"(b1_))

// ---------------------------------------------------------------------------
// pack hidden (also zeroes out — same index space)
// ---------------------------------------------------------------------------
__global__ void k_pack_hid(const float* __restrict__ hid, float* __restrict__ out) {
    int i = blockIdx.x * 256 + threadIdx.x;           // T*HP/4 units
    const float4* s = (const float4*)hid + (size_t)i * 2;
    float4 a = s[0], b = s[1];
    uint4 Hh, Mm;
    split_pack16(a.x, a.y, Hh.x, Mm.x);
    split_pack16(a.z, a.w, Hh.y, Mm.y);
    split_pack16(b.x, b.y, Hh.z, Mm.z);
    split_pack16(b.z, b.w, Hh.w, Mm.w);
    ((uint4*)g_hidH)[i] = Hh;
    ((uint4*)g_hidM)[i] = Mm;
    float4 z = make_float4(0.f, 0.f, 0.f, 0.f);
    ((float4*)out)[2 * i]     = z;
    ((float4*)out)[2 * i + 1] = z;
}

__global__ void k_route(const float* __restrict__ logits) {
    __shared__ int cnt[E_], cur[E_], soff[E_ + 1];
    int t = threadIdx.x;
    if (t < E_) { cnt[t] = 0; cur[t] = 0; }
    if (t < E_ * MAXMT) g_done1[t] = 0;
    if (t == 0) g_work = 0;
    __syncthreads();
    float l[E_];
#pragma unroll
    for (int e = 0; e < E_; e++) l[e] = logits[t * E_ + e];
    int i0 = 0;
#pragma unroll
    for (int e = 1; e < E_; e++) if (l[e] > l[i0]) i0 = e;
    int i1 = -1;
#pragma unroll
    for (int e = 0; e < E_; e++)
        if (e != i0 && (i1 < 0 || l[e] > l[i1])) i1 = e;
    g_pair_w[2 * t]     = 1.f / (1.f + expf(l[i1] - l[i0]));
    g_pair_w[2 * t + 1] = 1.f / (1.f + expf(l[i0] - l[i1]));
    atomicAdd(&cnt[i0], 1);
    atomicAdd(&cnt[i1], 1);
    __syncthreads();
    if (t == 0) {
        int o = 0;
        for (int e = 0; e < E_; e++) { soff[e] = o; o += cnt[e]; }
        soff[E_] = o;
    }
    __syncthreads();
    if (t <= E_) g_offsets[t] = soff[t];
    int p0 = atomicAdd(&cur[i0], 1);
    g_perm[soff[i0] + p0] = 2 * t;
    int p1 = atomicAdd(&cur[i1], 1);
    g_perm[soff[i1] + p1] = 2 * t + 1;
}

// merged weight packing (linear, coalesced)
#define NB13 (E_ * HP * 2 * I_ / 4 / 256)
#define NB2  (E_ * IP * H_ / 4 / 256)
__global__ void k_pack_w(const float* __restrict__ W13, const float* __restrict__ W2) {
    if (blockIdx.x < NB13) {
        size_t i = (size_t)blockIdx.x * 256 + threadIdx.x;
        int f4 = (int)(i & 511);
        size_t r = i >> 9;
        int hp = (int)(r & (HP - 1));
        int e  = (int)(r >> 9);
        const float* base = W13 + ((size_t)e * H_ + 2 * hp) * (2 * I_) + f4 * 4;
        float4 a = *(const float4*)base;
        float4 b = *(const float4*)(base + 2 * I_);
        uint4 Hh, Mm;
        split_pack16(a.x, b.x, Hh.x, Mm.x);
        split_pack16(a.y, b.y, Hh.y, Mm.y);
        split_pack16(a.z, b.z, Hh.z, Mm.z);
        split_pack16(a.w, b.w, Hh.w, Mm.w);
        ((uint4*)g_w13H)[i] = Hh;
        ((uint4*)g_w13M)[i] = Mm;
    } else {
        size_t i = (size_t)(blockIdx.x - NB13) * 256 + threadIdx.x;
        int f4 = (int)(i & 255);
        size_t r = i >> 8;
        int ip = (int)(r & (IP - 1));
        int e  = (int)(r >> 9);
        const float* base = W2 + ((size_t)e * I_ + 2 * ip) * H_ + f4 * 4;
        float4 a = *(const float4*)base;
        float4 b = *(const float4*)(base + H_);
        uint4 Hh, Mm;
        split_pack16(a.x, b.x, Hh.x, Mm.x);
        split_pack16(a.y, b.y, Hh.y, Mm.y);
        split_pack16(a.z, b.z, Hh.z, Mm.z);
        split_pack16(a.w, b.w, Hh.w, Mm.w);
        ((uint4*)g_w2H)[i] = Hh;
        ((uint4*)g_w2M)[i] = Mm;
    }
}

// ---------------------------------------------------------------------------
// Persistent MoE kernel: 148 resident blocks pull work items.
// items [0, NITEMS)        : gemm1 tile (emt = idx>>4, slab = idx&15)
// items [NITEMS, 2*NITEMS) : gemm2 tile (waits on g_done1[emt] == 16)
// ---------------------------------------------------------------------------
__global__ __launch_bounds__(256, 1) void k_moe(float* __restrict__ out) {
    extern __shared__ __align__(16) unsigned smem[];
    uint32_t sb = smem_u32(smem);
    int* s_pair = (int*)smem;                 // [128]
    __shared__ int s_item;

    int tid = threadIdx.x;
    int wid = tid >> 5, lane = tid & 31;
    int wm = wid >> 2, wn = wid & 3;          // 2 x 4 warps, tile 64x16
    int g = lane >> 2, tg = lane & 3;
    int ar = tid >> 2, aseg = (tid & 3) * 4;  // A staging
    int bkp = tid >> 4, bseg = (tid & 15) * 4;// B staging

    for (;;) {
        if (tid == 0) s_item = atomicAdd(&g_work, 1);
        __syncthreads();
        int idx = s_item;
        __syncthreads();                       // protect s_item reuse
        if (idx >= 2 * NITEMS) return;

        int is2  = idx >= NITEMS;
        int sub  = is2 ? idx - NITEMS : idx;
        int emt  = sub >> 4, slab = sub & 15;
        int e    = emt >> 4, mt = emt & 15;
        int off  = g_offsets[e], cnt = g_offsets[e + 1] - off;
        if (mt * BM >= cnt) continue;

        if (is2) {
            // wait for all 16 gemm1 slabs of this (e, mt)
            if (tid == 0) {
                while (atomicAdd(&g_done1[emt], 0) < 16) __nanosleep(100);
            }
            __syncthreads();
        }
        if (tid < BM) {
            int r = mt * BM + tid;
            s_pair[tid] = (r < cnt) ? g_perm[off + r] : -1;
        }
        __syncthreads();

        int n0 = slab * BN;

        if (!is2) {
            // ================= GEMM1 item =================
            size_t we = (size_t)e * HP * (2 * I_);
            float cgH[4][2][4] = {}, cgM[4][2][4] = {};
            float cuH[4][2][4] = {}, cuM[4][2][4] = {};

            auto stage = [&](int c) {
                uint32_t s0 = sb + (128 + (c & 1) * STW) * 4;
                int kof = c * BKP;
#pragma unroll
                for (int j = 0; j < 2; j++) {
                    int m = ar + j * 64;
                    int p = s_pair[m];
                    uint32_t sz = (p >= 0) ? 16u : 0u;
                    size_t so = (p >= 0) ? ((size_t)(p >> 1) * HP + kof + aseg) : 0;
                    uint32_t ad = s0 + (m * RS + aseg) * 4;
                    CP16(ad + OFF_AH * 4, g_hidH + so, sz);
                    CP16(ad + OFF_AM * 4, g_hidM + so, sz);
                }
                size_t bo = we + (size_t)(kof + bkp) * (2 * I_) + n0 + bseg;
                uint32_t bd = s0 + (bkp * BST + bseg) * 4;
                CP16(bd + OFF_B0 * 4, g_w13H + bo, 16);
                CP16(bd + OFF_B1 * 4, g_w13M + bo, 16);
                CP16(bd + OFF_B2 * 4, g_w13H + bo + I_, 16);
                CP16(bd + OFF_B3 * 4, g_w13M + bo + I_, 16);
                CP_COMMIT();
            };

            stage(0);
            for (int c = 0; c < NCH; c++) {
                CP_WAIT0();
                __syncthreads();
                if (c + 1 < NCH) stage(c + 1);
                unsigned* st = smem + 128 + (c & 1) * STW;
#pragma unroll
                for (int ks = 0; ks < 2; ks++) {
                    int kp0 = ks * 8;
                    unsigned bgh[2][2], bgm[2][2], buh[2][2], bum[2][2];
#pragma unroll
                    for (int nf = 0; nf < 2; nf++) {
                        int c0 = (kp0 + tg) * BST + wn * 16 + nf * 8 + g;
                        int c1 = c0 + 4 * BST;
                        bgh[nf][0] = st[OFF_B0 + c0]; bgh[nf][1] = st[OFF_B0 + c1];
                        bgm[nf][0] = st[OFF_B1 + c0]; bgm[nf][1] = st[OFF_B1 + c1];
                        buh[nf][0] = st[OFF_B2 + c0]; buh[nf][1] = st[OFF_B2 + c1];
                        bum[nf][0] = st[OFF_B3 + c0]; bum[nf][1] = st[OFF_B3 + c1];
                    }
#pragma unroll
                    for (int mf = 0; mf < 4; mf++) {
                        int r0 = (wm * 64 + mf * 16 + g) * RS + kp0 + tg;
                        int r1 = r0 + 8 * RS;
                        unsigned ah[4] = {st[OFF_AH+r0], st[OFF_AH+r1], st[OFF_AH+r0+4], st[OFF_AH+r1+4]};
                        unsigned am[4] = {st[OFF_AM+r0], st[OFF_AM+r1], st[OFF_AM+r0+4], st[OFF_AM+r1+4]};
#pragma unroll
                        for (int nf = 0; nf < 2; nf++) {
                            MMA(cgH[mf][nf], ah, bgh[nf][0], bgh[nf][1]);
                            MMA(cgM[mf][nf], am, bgm[nf][0], bgm[nf][1]);
                            MMA(cuH[mf][nf], ah, buh[nf][0], buh[nf][1]);
                            MMA(cuM[mf][nf], am, bum[nf][0], bum[nf][1]);
                        }
                    }
                }
            }

            // epilogue: combine, silu(gate)*up -> packed fp16 H/M act
            int pcb = (n0 >> 1) + wn * 8;
#pragma unroll
            for (int mf = 0; mf < 4; mf++) {
#pragma unroll
                for (int half = 0; half < 2; half++) {
                    int p = s_pair[wm * 64 + mf * 16 + g + half * 8];
                    if (p < 0) continue;
                    size_t rowo = (size_t)p * IP;
#pragma unroll
                    for (int nf = 0; nf < 2; nf++) {
                        float g0 = SC_C * cgH[mf][nf][half*2+0] + SC_S * cgM[mf][nf][half*2+0];
                        float g1 = SC_C * cgH[mf][nf][half*2+1] + SC_S * cgM[mf][nf][half*2+1];
                        float u0 = SC_C * cuH[mf][nf][half*2+0] + SC_S * cuM[mf][nf][half*2+0];
                        float u1 = SC_C * cuH[mf][nf][half*2+1] + SC_S * cuM[mf][nf][half*2+1];
                        float a0 = u0 * g0 / (1.f + expf(-g0));
                        float a1 = u1 * g1 / (1.f + expf(-g1));
                        unsigned hh, mm;
                        split_pack16(a0, a1, hh, mm);
                        int cidx = pcb + nf * 4 + tg;
                        g_actH[rowo + cidx] = hh;
                        g_actM[rowo + cidx] = mm;
                    }
                }
            }
            __syncthreads();
            if (tid == 0) { __threadfence(); atomicAdd(&g_done1[emt], 1); }
        } else {
            // ================= GEMM2 item =================
            size_t we = (size_t)e * IP * H_;
            float ccH[4][2][4] = {}, ccM[4][2][4] = {};

            auto stage = [&](int c) {
                uint32_t s0 = sb + (128 + (c & 1) * STW) * 4;
                int kof = c * BKP;
#pragma unroll
                for (int j = 0; j < 2; j++) {
                    int m = ar + j * 64;
                    int p = s_pair[m];
                    uint32_t sz = (p >= 0) ? 16u : 0u;
                    size_t so = (p >= 0) ? ((size_t)p * IP + kof + aseg) : 0;
                    uint32_t ad = s0 + (m * RS + aseg) * 4;
                    CP16(ad + OFF_AH * 4, g_actH + so, sz);
                    CP16(ad + OFF_AM * 4, g_actM + so, sz);
                }
                size_t bo = we + (size_t)(kof + bkp) * H_ + n0 + bseg;
                uint32_t bd = s0 + (bkp * BST + bseg) * 4;
                CP16(bd + OFF_B0 * 4, g_w2H + bo, 16);
                CP16(bd + OFF_B1 * 4, g_w2M + bo, 16);
                CP_COMMIT();
            };

            stage(0);
            for (int c = 0; c < NCH; c++) {
                CP_WAIT0();
                __syncthreads();
                if (c + 1 < NCH) stage(c + 1);
                unsigned* st = smem + 128 + (c & 1) * STW;
#pragma unroll
                for (int ks = 0; ks < 2; ks++) {
                    int kp0 = ks * 8;
                    unsigned bh[2][2], bm[2][2];
#pragma unroll
                    for (int nf = 0; nf < 2; nf++) {
                        int c0 = (kp0 + tg) * BST + wn * 16 + nf * 8 + g;
                        int c1 = c0 + 4 * BST;
                        bh[nf][0] = st[OFF_B0 + c0]; bh[nf][1] = st[OFF_B0 + c1];
                        bm[nf][0] = st[OFF_B1 + c0]; bm[nf][1] = st[OFF_B1 + c1];
                    }
#pragma unroll
                    for (int mf = 0; mf < 4; mf++) {
                        int r0 = (wm * 64 + mf * 16 + g) * RS + kp0 + tg;
                        int r1 = r0 + 8 * RS;
                        unsigned ah[4] = {st[OFF_AH+r0], st[OFF_AH+r1], st[OFF_AH+r0+4], st[OFF_AH+r1+4]};
                        unsigned am[4] = {st[OFF_AM+r0], st[OFF_AM+r1], st[OFF_AM+r0+4], st[OFF_AM+r1+4]};
#pragma unroll
                        for (int nf = 0; nf < 2; nf++) {
                            MMA(ccH[mf][nf], ah, bh[nf][0], bh[nf][1]);
                            MMA(ccM[mf][nf], am, bm[nf][0], bm[nf][1]);
                        }
                    }
                }
            }

#pragma unroll
            for (int mf = 0; mf < 4; mf++) {
#pragma unroll
                for (int half = 0; half < 2; half++) {
                    int p = s_pair[wm * 64 + mf * 16 + g + half * 8];
                    if (p < 0) continue;
                    int   t = p >> 1;
                    float w = g_pair_w[p];
                    float* dst = out + (size_t)t * H_ + n0 + wn * 16 + 2 * tg;
#pragma unroll
                    for (int nf = 0; nf < 2; nf++) {
                        float r0 = SC_C * ccH[mf][nf][half*2+0] + SC_S * ccM[mf][nf][half*2+0];
                        float r1 = SC_C * ccH[mf][nf][half*2+1] + SC_S * ccM[mf][nf][half*2+1];
                        atomicAdd(&dst[nf * 8],     w * r0);
                        atomicAdd(&dst[nf * 8 + 1], w * r1);
                    }
                }
            }
        }
    }
}

// ---------------------------------------------------------------------------
extern "C" void kernel_launch(void* const* d_in, const int* in_sizes, int n_in,
                              void* d_out, int out_size) {
    const float* hid    = (const float*)d_in[0];   // [T, H]
    const float* logits = (const float*)d_in[1];   // [T, E]
    const float* W13    = (const float*)d_in[2];   // [E, H, 2I]
    const float* W2     = (const float*)d_in[3];   // [E, I, H]
    float* out = (float*)d_out;                    // [T, H]

    cudaFuncSetAttribute(k_moe, cudaFuncAttributeMaxDynamicSharedMemorySize, SM_BYTES);

    k_pack_hid<<<(T_ * HP / 4) / 256, 256>>>(hid, out);
    k_route<<<1, 1024>>>(logits);
    k_pack_w<<<NB13 + NB2, 256>>>(W13, W2);

    k_moe<<<NBLK, 256, SM_BYTES>>>(out);
}

// round 15
// speedup vs baseline: 1.1436x; 1.1436x over previous
#include <cuda_runtime.h>
#include <cuda_fp16.h>
#include <math.h>
#include <stdint.h>

#define T_ 1024
#define H_ 1024
#define I_ 1024
#define E_ 8
#define NP (T_*2)
#define HP (H_/2)      // 512 packed k-pairs per row
#define IP (I_/2)

#define BM 128
#define BN 64
#define BKP 16         // k-pairs per chunk (32 floats)
#define RS 20          // A smem row stride (words) — conflict-free frags
#define BST 72         // B smem kp-row stride (words) — conflict-free frags
#define MAXMT 16
#define NCH 32         // 512 kp / 16

// combine constants: D = (1 - 1/s)*C_HH + s*C_MM, s = 32
#define SC_C 0.96875f
#define SC_S 32.0f
#define SC_INV 0.03125f

// stage word offsets (within one stage)
#define OFF_AH 0
#define OFF_AM 2560
#define OFF_B0 5120          // gemm1: gate-H ; gemm2: w2-H
#define OFF_B1 6272          // gemm1: gate-M ; gemm2: w2-M
#define OFF_B2 7424          // gemm1: up-H
#define OFF_B3 8576          // gemm1: up-M
#define STW1 9728            // stage words gemm1
#define STW2 7424            // stage words gemm2
#define SM1_BYTES ((128 + 2*STW1)*4)
#define SM2_BYTES ((128 + 2*STW2)*4)

// ---- routing scratch ----
__device__ float g_pair_w[NP];
__device__ int   g_offsets[E_+1];
__device__ int   g_perm[NP];
__device__ int   g_cnt[E_], g_cur[E_];

// ---- packed fp16 hi / scaled-residual operands (uint32 = half2 k-pair) ----
__device__ __align__(16) unsigned g_hidH[T_*HP],        g_hidM[T_*HP];        // [t][hp]
__device__ __align__(16) unsigned g_w13H[E_*HP*2*I_],   g_w13M[E_*HP*2*I_];   // [e][hp][2I]
__device__ __align__(16) unsigned g_w2H [E_*IP*H_],     g_w2M [E_*IP*H_];     // [e][ip][H]
__device__ __align__(16) unsigned g_actH[NP*IP],        g_actM[NP*IP];        // [p][ip]

// ---------------------------------------------------------------------------
__device__ __forceinline__ void split_pack16(float x, float y, unsigned& h, unsigned& m) {
    __half2 hv = __floats2half2_rn(x, y);
    h = *(unsigned*)&hv;
    float hx = __low2float(hv), hy = __high2float(hv);
    __half2 mv = __floats2half2_rn(hx * SC_INV + (x - hx), hy * SC_INV + (y - hy));
    m = *(unsigned*)&mv;
}
__device__ __forceinline__ uint32_t smem_u32(const void* p) {
    uint32_t a;
    asm("{ .reg .u64 t; cvta.to.shared.u64 t, %1; cvt.u32.u64 %0, t; }" : "=r"(a) : "l"(p));
    return a;
}
#define CP16(dst, src, sz) \
    asm volatile("cp.async.cg.shared.global [%0], [%1], 16, %2;" :: "r"(dst), "l"(src), "r"(sz) : "memory")
#define CP_COMMIT() asm volatile("cp.async.commit_group;" ::: "memory")
#define CP_WAIT0()  asm volatile("cp.async.wait_group 0;" ::: "memory")

#define MMA(c, a, b0_, b1_)                                                   \
    asm volatile("mma.sync.aligned.m16n8k16.row.col.f32.f16.f16.f32 "         \
        "{%0,%1,%2,%3}, {%4,%5,%6,%7}, {%8,%9}, {%0,%1,%2,%3};"               \
        : "+f"((c)[0]), "+f"((c)[1]), "+f"((c)[2]), "+f"((c)[3])              \
        : "r"((a)[0]), "r"((a)[1]), "r"((a)[2]), "r"((a)[3]),                 \
          "r"(b0_), "r"(b1_))

// ---------------------------------------------------------------------------
// pack hidden + zero output + (block 0) routing
// ---------------------------------------------------------------------------
__global__ void k_pack_hid(const float* __restrict__ hid, float* __restrict__ out,
                           const float* __restrict__ logits) {
    int tid = threadIdx.x;
    int i = blockIdx.x * 256 + tid;                   // T*HP/4 units
    const float4* s = (const float4*)hid + (size_t)i * 2;
    float4 a = s[0], b = s[1];
    uint4 Hh, Mm;
    split_pack16(a.x, a.y, Hh.x, Mm.x);
    split_pack16(a.z, a.w, Hh.y, Mm.y);
    split_pack16(b.x, b.y, Hh.z, Mm.z);
    split_pack16(b.z, b.w, Hh.w, Mm.w);
    ((uint4*)g_hidH)[i] = Hh;
    ((uint4*)g_hidM)[i] = Mm;
    float4 z = make_float4(0.f, 0.f, 0.f, 0.f);
    ((float4*)out)[2 * i]     = z;
    ((float4*)out)[2 * i + 1] = z;

    if (blockIdx.x != 0) return;
    // ---- routing: 256 threads x 4 tokens ----
    if (tid < E_) { g_cnt[tid] = 0; g_cur[tid] = 0; }
    __syncthreads();
    int sel0[4], sel1[4];
    float w0v[4], w1v[4];
#pragma unroll
    for (int j = 0; j < 4; j++) {
        int t = tid * 4 + j;
        float l[E_];
#pragma unroll
        for (int e = 0; e < E_; e++) l[e] = logits[t * E_ + e];
        int i0 = 0;
#pragma unroll
        for (int e = 1; e < E_; e++) if (l[e] > l[i0]) i0 = e;
        int i1 = -1;
#pragma unroll
        for (int e = 0; e < E_; e++)
            if (e != i0 && (i1 < 0 || l[e] > l[i1])) i1 = e;
        sel0[j] = i0; sel1[j] = i1;
        w0v[j] = 1.f / (1.f + expf(l[i1] - l[i0]));
        w1v[j] = 1.f / (1.f + expf(l[i0] - l[i1]));
        g_pair_w[2 * t]     = w0v[j];
        g_pair_w[2 * t + 1] = w1v[j];
        atomicAdd(&g_cnt[i0], 1);
        atomicAdd(&g_cnt[i1], 1);
    }
    __syncthreads();
    __shared__ int soff[E_ + 1];
    if (tid == 0) {
        int o = 0;
        for (int e = 0; e < E_; e++) { soff[e] = o; o += g_cnt[e]; }
        soff[E_] = o;
    }
    __syncthreads();
    if (tid <= E_) g_offsets[tid] = soff[tid];
#pragma unroll
    for (int j = 0; j < 4; j++) {
        int t = tid * 4 + j;
        int p0 = atomicAdd(&g_cur[sel0[j]], 1);
        g_perm[soff[sel0[j]] + p0] = 2 * t;
        int p1 = atomicAdd(&g_cur[sel1[j]], 1);
        g_perm[soff[sel1[j]] + p1] = 2 * t + 1;
    }
}

// W13 packing only (linear, coalesced)
#define NB13 (E_ * HP * 2 * I_ / 4 / 256)
__global__ void k_pack_w13(const float* __restrict__ W13) {
    size_t i = (size_t)blockIdx.x * 256 + threadIdx.x;
    int f4 = (int)(i & 511);
    size_t r = i >> 9;
    int hp = (int)(r & (HP - 1));
    int e  = (int)(r >> 9);
    const float* base = W13 + ((size_t)e * H_ + 2 * hp) * (2 * I_) + f4 * 4;
    float4 a = *(const float4*)base;
    float4 b = *(const float4*)(base + 2 * I_);
    uint4 Hh, Mm;
    split_pack16(a.x, b.x, Hh.x, Mm.x);
    split_pack16(a.y, b.y, Hh.y, Mm.y);
    split_pack16(a.z, b.z, Hh.z, Mm.z);
    split_pack16(a.w, b.w, Hh.w, Mm.w);
    ((uint4*)g_w13H)[i] = Hh;
    ((uint4*)g_w13M)[i] = Mm;
}

// ---------------------------------------------------------------------------
// GEMM1: act = silu(X@Wg)*(X@Wu). Also piggybacks W2 packing across its grid
// (every block packs 512 uint4 units before its GEMM work; 2048*512 = 1M = all
// of W2; gemm2 runs in the next kernel so ordering is stream-guaranteed).
// ---------------------------------------------------------------------------
__global__ __launch_bounds__(256, 1) void k_gemm1(const float* __restrict__ W2) {
    extern __shared__ __align__(16) unsigned smem[];
    uint32_t sb = smem_u32(smem);
    int* s_pair = (int*)smem;                 // [128]
    int tid = threadIdx.x;

    // ---- piggyback W2 -> fp16 H/M packing (2 units per thread) ----
    {
        size_t u = ((size_t)blockIdx.y * gridDim.x + blockIdx.x) * 512 + (size_t)tid * 2;
#pragma unroll
        for (int j = 0; j < 2; j++) {
            size_t i = u + j;
            int f4 = (int)(i & 255);
            size_t r = i >> 8;
            int ip = (int)(r & (IP - 1));
            int e2 = (int)(r >> 9);
            const float* base = W2 + ((size_t)e2 * I_ + 2 * ip) * H_ + f4 * 4;
            float4 a = *(const float4*)base;
            float4 b = *(const float4*)(base + H_);
            uint4 Hh, Mm;
            split_pack16(a.x, b.x, Hh.x, Mm.x);
            split_pack16(a.y, b.y, Hh.y, Mm.y);
            split_pack16(a.z, b.z, Hh.z, Mm.z);
            split_pack16(a.w, b.w, Hh.w, Mm.w);
            ((uint4*)g_w2H)[i] = Hh;
            ((uint4*)g_w2M)[i] = Mm;
        }
    }

    int e  = blockIdx.y >> 4;
    int mt = blockIdx.y & 15;
    int off = g_offsets[e], cnt = g_offsets[e + 1] - off;
    if (mt * BM >= cnt) return;

    if (tid < BM) {
        int r = mt * BM + tid;
        s_pair[tid] = (r < cnt) ? g_perm[off + r] : -1;
    }
    __syncthreads();

    int n0 = blockIdx.x * BN;
    size_t we = (size_t)e * HP * (2 * I_);

    int wid = tid >> 5, lane = tid & 31;
    int wm = wid >> 2, wn = wid & 3;
    int g = lane >> 2, tg = lane & 3;
    int ar = tid >> 2, aseg = (tid & 3) * 4;  // A staging
    int bkp = tid >> 4, bseg = (tid & 15) * 4;// B staging

    float cgH[4][2][4] = {}, cgM[4][2][4] = {};
    float cuH[4][2][4] = {}, cuM[4][2][4] = {};

    auto stage = [&](int c) {
        uint32_t s0 = sb + (128 + (c & 1) * STW1) * 4;
        int kof = c * BKP;
#pragma unroll
        for (int j = 0; j < 2; j++) {
            int m = ar + j * 64;
            int p = s_pair[m];
            uint32_t sz = (p >= 0) ? 16u : 0u;
            size_t so = (p >= 0) ? ((size_t)(p >> 1) * HP + kof + aseg) : 0;
            uint32_t ad = s0 + (m * RS + aseg) * 4;
            CP16(ad + OFF_AH * 4, g_hidH + so, sz);
            CP16(ad + OFF_AM * 4, g_hidM + so, sz);
        }
        size_t bo = we + (size_t)(kof + bkp) * (2 * I_) + n0 + bseg;
        uint32_t bd = s0 + (bkp * BST + bseg) * 4;
        CP16(bd + OFF_B0 * 4, g_w13H + bo, 16);
        CP16(bd + OFF_B1 * 4, g_w13M + bo, 16);
        CP16(bd + OFF_B2 * 4, g_w13H + bo + I_, 16);
        CP16(bd + OFF_B3 * 4, g_w13M + bo + I_, 16);
        CP_COMMIT();
    };

    stage(0);
    for (int c = 0; c < NCH; c++) {
        CP_WAIT0();
        __syncthreads();
        if (c + 1 < NCH) stage(c + 1);
        unsigned* st = smem + 128 + (c & 1) * STW1;
#pragma unroll
        for (int ks = 0; ks < 2; ks++) {
            int kp0 = ks * 8;
            unsigned bgh[2][2], bgm[2][2], buh[2][2], bum[2][2];
#pragma unroll
            for (int nf = 0; nf < 2; nf++) {
                int c0 = (kp0 + tg) * BST + wn * 16 + nf * 8 + g;
                int c1 = c0 + 4 * BST;
                bgh[nf][0] = st[OFF_B0 + c0]; bgh[nf][1] = st[OFF_B0 + c1];
                bgm[nf][0] = st[OFF_B1 + c0]; bgm[nf][1] = st[OFF_B1 + c1];
                buh[nf][0] = st[OFF_B2 + c0]; buh[nf][1] = st[OFF_B2 + c1];
                bum[nf][0] = st[OFF_B3 + c0]; bum[nf][1] = st[OFF_B3 + c1];
            }
#pragma unroll
            for (int mf = 0; mf < 4; mf++) {
                int r0 = (wm * 64 + mf * 16 + g) * RS + kp0 + tg;
                int r1 = r0 + 8 * RS;
                unsigned ah[4] = {st[OFF_AH+r0], st[OFF_AH+r1], st[OFF_AH+r0+4], st[OFF_AH+r1+4]};
                unsigned am[4] = {st[OFF_AM+r0], st[OFF_AM+r1], st[OFF_AM+r0+4], st[OFF_AM+r1+4]};
#pragma unroll
                for (int nf = 0; nf < 2; nf++) {
                    MMA(cgH[mf][nf], ah, bgh[nf][0], bgh[nf][1]);
                    MMA(cgM[mf][nf], am, bgm[nf][0], bgm[nf][1]);
                    MMA(cuH[mf][nf], ah, buh[nf][0], buh[nf][1]);
                    MMA(cuM[mf][nf], am, bum[nf][0], bum[nf][1]);
                }
            }
        }
    }

    // epilogue: combine, silu(gate)*up -> packed fp16 H/M act
    int pcb = (n0 >> 1) + wn * 8;
#pragma unroll
    for (int mf = 0; mf < 4; mf++) {
#pragma unroll
        for (int half = 0; half < 2; half++) {
            int p = s_pair[wm * 64 + mf * 16 + g + half * 8];
            if (p < 0) continue;
            size_t rowo = (size_t)p * IP;
#pragma unroll
            for (int nf = 0; nf < 2; nf++) {
                float g0 = SC_C * cgH[mf][nf][half*2+0] + SC_S * cgM[mf][nf][half*2+0];
                float g1 = SC_C * cgH[mf][nf][half*2+1] + SC_S * cgM[mf][nf][half*2+1];
                float u0 = SC_C * cuH[mf][nf][half*2+0] + SC_S * cuM[mf][nf][half*2+0];
                float u1 = SC_C * cuH[mf][nf][half*2+1] + SC_S * cuM[mf][nf][half*2+1];
                float a0 = u0 * g0 / (1.f + expf(-g0));
                float a1 = u1 * g1 / (1.f + expf(-g1));
                unsigned hh, mm;
                split_pack16(a0, a1, hh, mm);
                int cidx = pcb + nf * 4 + tg;
                g_actH[rowo + cidx] = hh;
                g_actM[rowo + cidx] = mm;
            }
        }
    }
}

// ---------------------------------------------------------------------------
// GEMM2: out[t] += w_p * (act[p] @ W2[e]); 2-MMA fp16 split
// ---------------------------------------------------------------------------
__global__ __launch_bounds__(256, 2) void k_gemm2(float* __restrict__ out) {
    extern __shared__ __align__(16) unsigned smem[];
    uint32_t sb = smem_u32(smem);
    int* s_pair = (int*)smem;

    int e  = blockIdx.y >> 4;
    int mt = blockIdx.y & 15;
    int off = g_offsets[e], cnt = g_offsets[e + 1] - off;
    if (mt * BM >= cnt) return;

    int tid = threadIdx.x;
    if (tid < BM) {
        int r = mt * BM + tid;
        s_pair[tid] = (r < cnt) ? g_perm[off + r] : -1;
    }
    __syncthreads();

    int n0 = blockIdx.x * BN;
    size_t we = (size_t)e * IP * H_;

    int wid = tid >> 5, lane = tid & 31;
    int wm = wid >> 2, wn = wid & 3;
    int g = lane >> 2, tg = lane & 3;
    int ar = tid >> 2, aseg = (tid & 3) * 4;
    int bkp = tid >> 4, bseg = (tid & 15) * 4;

    float ccH[4][2][4] = {}, ccM[4][2][4] = {};

    auto stage = [&](int c) {
        uint32_t s0 = sb + (128 + (c & 1) * STW2) * 4;
        int kof = c * BKP;
#pragma unroll
        for (int j = 0; j < 2; j++) {
            int m = ar + j * 64;
            int p = s_pair[m];
            uint32_t sz = (p >= 0) ? 16u : 0u;
            size_t so = (p >= 0) ? ((size_t)p * IP + kof + aseg) : 0;
            uint32_t ad = s0 + (m * RS + aseg) * 4;
            CP16(ad + OFF_AH * 4, g_actH + so, sz);
            CP16(ad + OFF_AM * 4, g_actM + so, sz);
        }
        size_t bo = we + (size_t)(kof + bkp) * H_ + n0 + bseg;
        uint32_t bd = s0 + (bkp * BST + bseg) * 4;
        CP16(bd + OFF_B0 * 4, g_w2H + bo, 16);
        CP16(bd + OFF_B1 * 4, g_w2M + bo, 16);
        CP_COMMIT();
    };

    stage(0);
    for (int c = 0; c < NCH; c++) {
        CP_WAIT0();
        __syncthreads();
        if (c + 1 < NCH) stage(c + 1);
        unsigned* st = smem + 128 + (c & 1) * STW2;
#pragma unroll
        for (int ks = 0; ks < 2; ks++) {
            int kp0 = ks * 8;
            unsigned bh[2][2], bm[2][2];
#pragma unroll
            for (int nf = 0; nf < 2; nf++) {
                int c0 = (kp0 + tg) * BST + wn * 16 + nf * 8 + g;
                int c1 = c0 + 4 * BST;
                bh[nf][0] = st[OFF_B0 + c0]; bh[nf][1] = st[OFF_B0 + c1];
                bm[nf][0] = st[OFF_B1 + c0]; bm[nf][1] = st[OFF_B1 + c1];
            }
#pragma unroll
            for (int mf = 0; mf < 4; mf++) {
                int r0 = (wm * 64 + mf * 16 + g) * RS + kp0 + tg;
                int r1 = r0 + 8 * RS;
                unsigned ah[4] = {st[OFF_AH+r0], st[OFF_AH+r1], st[OFF_AH+r0+4], st[OFF_AH+r1+4]};
                unsigned am[4] = {st[OFF_AM+r0], st[OFF_AM+r1], st[OFF_AM+r0+4], st[OFF_AM+r1+4]};
#pragma unroll
                for (int nf = 0; nf < 2; nf++) {
                    MMA(ccH[mf][nf], ah, bh[nf][0], bh[nf][1]);
                    MMA(ccM[mf][nf], am, bm[nf][0], bm[nf][1]);
                }
            }
        }
    }

#pragma unroll
    for (int mf = 0; mf < 4; mf++) {
#pragma unroll
        for (int half = 0; half < 2; half++) {
            int p = s_pair[wm * 64 + mf * 16 + g + half * 8];
            if (p < 0) continue;
            int   t = p >> 1;
            float w = g_pair_w[p];
            float* dst = out + (size_t)t * H_ + n0 + wn * 16 + 2 * tg;
#pragma unroll
            for (int nf = 0; nf < 2; nf++) {
                float r0 = SC_C * ccH[mf][nf][half*2+0] + SC_S * ccM[mf][nf][half*2+0];
                float r1 = SC_C * ccH[mf][nf][half*2+1] + SC_S * ccM[mf][nf][half*2+1];
                atomicAdd(&dst[nf * 8],     w * r0);
                atomicAdd(&dst[nf * 8 + 1], w * r1);
            }
        }
    }
}

// ---------------------------------------------------------------------------
extern "C" void kernel_launch(void* const* d_in, const int* in_sizes, int n_in,
                              void* d_out, int out_size) {
    const float* hid    = (const float*)d_in[0];   // [T, H]
    const float* logits = (const float*)d_in[1];   // [T, E]
    const float* W13    = (const float*)d_in[2];   // [E, H, 2I]
    const float* W2     = (const float*)d_in[3];   // [E, I, H]
    float* out = (float*)d_out;                    // [T, H]

    cudaFuncSetAttribute(k_gemm1, cudaFuncAttributeMaxDynamicSharedMemorySize, SM1_BYTES);
    cudaFuncSetAttribute(k_gemm2, cudaFuncAttributeMaxDynamicSharedMemorySize, SM2_BYTES);

    k_pack_hid<<<(T_ * HP / 4) / 256, 256>>>(hid, out, logits);
    k_pack_w13<<<NB13, 256>>>(W13);

    dim3 g1(I_ / BN, E_ * MAXMT);
    k_gemm1<<<g1, 256, SM1_BYTES>>>(W2);
    dim3 g2(H_ / BN, E_ * MAXMT);
    k_gemm2<<<g2, 256, SM2_BYTES>>>(out);
}